// round 7
// baseline (speedup 1.0000x reference)
#include <cuda_runtime.h>

// Problem constants
#define N_LEN   131072
#define B_ROWS  256

// Tiling
#define TPB     128
#define EPT     16                     // output pairs per thread per pass
#define CHUNK   (TPB*EPT)              // 2048 positions per chunk per row-pair
#define NCHUNK  4                      // chunks per block (software pipeline depth 2)
#define IN_PAIRS  (CHUNK + 32)         // 2080  (x halo: 32)
#define V_PAIRS   (CHUNK + 16)         // 2064  (v halo: 16)
#define PAD16(n)  ((((n) + 15) / 16) * 17)
#define IN_PAD    PAD16(IN_PAIRS)      // 2210
#define V_PAD     PAD16(V_PAIRS)       // 2193
#define SMEM_U64  (2*IN_PAD + V_PAD)   // double-buffered x + single v
#define SMEM_BYTES (SMEM_U64 * 8)      // 52904 B

typedef unsigned long long u64;

__device__ __forceinline__ u64 pack2(float a, float b) {
    u64 r; asm("mov.b64 %0,{%1,%2};" : "=l"(r) : "f"(a), "f"(b)); return r;
}
__device__ __forceinline__ void unpack2(u64 v, float& a, float& b) {
    asm("mov.b64 {%0,%1},%2;" : "=f"(a), "=f"(b) : "l"(v));
}
__device__ __forceinline__ u64 fma2(u64 a, u64 b, u64 c) {
    u64 d; asm("fma.rn.f32x2 %0,%1,%2,%3;" : "=l"(d) : "l"(a), "l"(b), "l"(c)); return d;
}
__device__ __forceinline__ u64 mul2(u64 a, u64 b) {
    u64 d; asm("mul.rn.f32x2 %0,%1,%2;" : "=l"(d) : "l"(a), "l"(b)); return d;
}
__device__ __forceinline__ u64 add2(u64 a, u64 b) {
    u64 d; asm("add.rn.f32x2 %0,%1,%2;" : "=l"(d) : "l"(a), "l"(b)); return d;
}

// pad-17-per-16 swizzle: conflict-free for stride-16 u64 lane patterns
__device__ __forceinline__ int sw(int idx) { return (idx >> 4) * 17 + (idx & 15); }

// stage one chunk's x window (incl. 32-pair halo) into dst, pair-packed
__device__ __forceinline__ void stage_x(u64* __restrict__ dst, int c0, int tid,
                                        const float* __restrict__ x0,
                                        const float* __restrict__ x1) {
#pragma unroll
    for (int it = 0; it < 5; it++) {
        int grp = tid + it * TPB;              // float4 group index (520 groups)
        if (grp * 4 < IN_PAIRS) {
            int base = grp * 4;
            int p = c0 - 32 + base;            // <0 only for the very first chunk
            float4 a0, a1;
            if (p >= 0) {
                a0 = *reinterpret_cast<const float4*>(x0 + p);
                a1 = *reinterpret_cast<const float4*>(x1 + p);
            } else {
                a0 = make_float4(0.f, 0.f, 0.f, 0.f);
                a1 = make_float4(0.f, 0.f, 0.f, 0.f);
            }
            int ph = sw(base);                 // base 4-aligned -> contiguous slots
            dst[ph + 0] = pack2(a0.x, a1.x);
            dst[ph + 1] = pack2(a0.y, a1.y);
            dst[ph + 2] = pack2(a0.z, a1.z);
            dst[ph + 3] = pack2(a0.w, a1.w);
        }
    }
}

__global__ void __launch_bounds__(TPB, 4) fir2(const float* __restrict__ x,
                                               const float* __restrict__ h,
                                               float* __restrict__ y) {
    extern __shared__ u64 smem[];
    u64* bufA = smem;                 // x / y-staging buffer, slot 0
    u64* bufB = smem + IN_PAD;        // x / y-staging buffer, slot 1
    u64* sV   = smem + 2 * IN_PAD;    // v-pairs at pos (c0 - 16 + k)

    const int tid  = threadIdx.x;
    const int pair = blockIdx.y;
    const int cb0  = blockIdx.x * (NCHUNK * CHUNK);   // first chunk base position
    const float* __restrict__ x0 = x + (size_t)(2 * pair) * N_LEN;
    const float* __restrict__ x1 = x0 + N_LEN;
    float* __restrict__ y0 = y + (size_t)(2 * pair) * N_LEN;
    float* __restrict__ y1 = y0 + N_LEN;

    // 16 packed coefficients (h[j],h[j]) — pass 2 uses reversed indexing h[15-j]
    u64 gph[16];
#pragma unroll
    for (int j = 0; j < 16; j++) { float hv = __ldg(h + j); gph[j] = pack2(hv, hv); }

    const int lo = tid * EPT;

    // prologue: stage chunk 0
    stage_x(bufA, cb0, tid, x0, x1);

#pragma unroll 1
    for (int cc = 0; cc < NCHUNK; cc++) {
        u64* cur = (cc & 1) ? bufB : bufA;
        u64* nxt = (cc & 1) ? bufA : bufB;
        const int c0 = cb0 + cc * CHUNK;
        const bool kill = (c0 == 0) && (tid == 0);   // positions 0..15 masked to 0

        __syncthreads();                              // cur staged; nxt free of readers

        // prefetch next chunk under this chunk's compute
        if (cc + 1 < NCHUNK) stage_x(nxt, c0 + CHUNK, tid, x0, x1);

        // ---- pass 1: v[p] = x[p] + sum_{j=0..15} h[j]*x[p-1-j]; kept in regs ----
        u64 vbuf[16];
        {
            u64 r[16];                                // x ring: x[q] at slot q&15
#pragma unroll
            for (int s = 0; s < 16; s++) r[s] = cur[sw(lo + 16 + s)];

#pragma unroll
            for (int t = 0; t < EPT; t++) {
                u64 xi = cur[sw(lo + 32 + t)];
                u64 acc0 = xi;
#pragma unroll
                for (int j = 0; j < 8; j++)
                    acc0 = fma2(gph[j], r[(t + 15 - j) & 15], acc0);
                u64 acc1 = mul2(gph[8], r[(t + 7) & 15]);
#pragma unroll
                for (int j = 9; j < 16; j++)
                    acc1 = fma2(gph[j], r[(t + 15 - j) & 15], acc1);
                vbuf[t] = add2(acc0, acc1);
                r[t & 15] = xi;
            }
        }
        if (kill) {
#pragma unroll
            for (int t = 0; t < EPT; t++) vbuf[t] = 0ULL;
        }
        // publish v for the next thread's halo
#pragma unroll
        for (int t = 0; t < EPT; t++) sV[sw(lo + 16 + t)] = vbuf[t];

        // pass-1 halo: v at pos (c0-16+tid) for tid<16, recomputed from x
        if (tid < 16) {
            int gp = c0 - 16 + tid;
            u64 v = 0ULL;
            if (gp >= 16) {
                u64 xi = cur[sw(16 + tid)];
                u64 a0 = xi;
#pragma unroll
                for (int j = 0; j < 8; j++)  a0 = fma2(gph[j], cur[sw(15 + tid - j)], a0);
                u64 a1 = mul2(gph[8], cur[sw(7 + tid)]);
#pragma unroll
                for (int j = 9; j < 16; j++) a1 = fma2(gph[j], cur[sw(15 + tid - j)], a1);
                v = add2(a0, a1);
            }
            sV[sw(tid)] = v;
        }
        __syncthreads();                              // sV ready; cur x-reads done

        // ---- pass 2: y[p] = v[p] + sum_j h[15-j]*v[p-1-j]; register window ----
        {
            u64 hv[16];                               // halo: v[c0+lo-16+s]
#pragma unroll
            for (int s = 0; s < 16; s++) hv[s] = sV[sw(lo + s)];

#pragma unroll
            for (int t = 0; t < EPT; t++) {
                u64 acc0 = vbuf[t];
#pragma unroll
                for (int j = 0; j < 8; j++) {         // tap v[lo+t-1-j]
                    int k = t - 1 - j;
                    u64 tap = (k >= 0) ? vbuf[k] : hv[16 + k];
                    acc0 = fma2(gph[15 - j], tap, acc0);
                }
                u64 tap8;
                { int k = t - 9; tap8 = (k >= 0) ? vbuf[k] : hv[16 + k]; }
                u64 acc1 = mul2(gph[7], tap8);
#pragma unroll
                for (int j = 9; j < 16; j++) {
                    int k = t - 1 - j;
                    u64 tap = (k >= 0) ? vbuf[k] : hv[16 + k];
                    acc1 = fma2(gph[15 - j], tap, acc1);
                }
                cur[sw(lo + t)] = add2(acc0, acc1);   // stage y into cur (x dead)
            }
        }
        if (kill) {
#pragma unroll
            for (int t = 0; t < EPT; t++) cur[sw(t)] = 0ULL;
        }
        __syncthreads();                              // y staged

        // ---- writeout: float4 coalesced stores ----
#pragma unroll
        for (int it = 0; it < 4; it++) {
            int base = (tid + it * TPB) * 4;
            int ph = sw(base);
            float a[4], b[4];
#pragma unroll
            for (int k = 0; k < 4; k++) unpack2(cur[ph + k], a[k], b[k]);
            *reinterpret_cast<float4*>(y0 + c0 + base) = make_float4(a[0], a[1], a[2], a[3]);
            *reinterpret_cast<float4*>(y1 + c0 + base) = make_float4(b[0], b[1], b[2], b[3]);
        }
    }
}

extern "C" void kernel_launch(void* const* d_in, const int* in_sizes, int n_in,
                              void* d_out, int out_size) {
    (void)in_sizes; (void)n_in; (void)out_size;
    const float* x = (const float*)d_in[0];
    const float* h = (const float*)d_in[1];
    float* y = (float*)d_out;

    cudaFuncSetAttribute(fir2, cudaFuncAttributeMaxDynamicSharedMemorySize, SMEM_BYTES);

    dim3 grid(N_LEN / (CHUNK * NCHUNK), B_ROWS / 2, 1);
    fir2<<<grid, TPB, SMEM_BYTES>>>(x, h, y);
}

// round 9
// speedup vs baseline: 1.0961x; 1.0961x over previous
#include <cuda_runtime.h>
#include <cstdint>

// Problem constants
#define N_LEN   131072
#define B_ROWS  256

// Tiling
#define TPB     128
#define EPT     16                      // output pairs per thread per pass
#define CHUNK   (TPB*EPT)               // 2048 positions per chunk
#define NCHUNK  4                       // chunks per block (cp.async pipeline)
#define IN_F    (CHUNK + 32)            // 2080 floats per row incl 32-halo
#define ROW_F   2212                    // padded row: 130*17=2210, +2 for row alignment

typedef unsigned long long u64;
typedef unsigned int u32;

__device__ __forceinline__ u64 pack2(float a, float b) {
    u64 r; asm("mov.b64 %0,{%1,%2};" : "=l"(r) : "f"(a), "f"(b)); return r;
}
__device__ __forceinline__ void unpack2(u64 v, float& a, float& b) {
    asm("mov.b64 {%0,%1},%2;" : "=f"(a), "=f"(b) : "l"(v));
}
__device__ __forceinline__ u64 fma2(u64 a, u64 b, u64 c) {
    u64 d; asm("fma.rn.f32x2 %0,%1,%2,%3;" : "=l"(d) : "l"(a), "l"(b), "l"(c)); return d;
}
__device__ __forceinline__ u64 mul2(u64 a, u64 b) {
    u64 d; asm("mul.rn.f32x2 %0,%1,%2;" : "=l"(d) : "l"(a), "l"(b)); return d;
}
__device__ __forceinline__ u64 add2(u64 a, u64 b) {
    u64 d; asm("add.rn.f32x2 %0,%1,%2;" : "=l"(d) : "l"(a), "l"(b)); return d;
}

// pad-17-per-16-float swizzle: float-stride-16 lane patterns -> addr stride 17 (odd) -> CF
__device__ __forceinline__ int sw(int i) { return (i >> 4) * 17 + (i & 15); }

__device__ __forceinline__ u32 sptr(const void* p) {
    u32 r; asm("{.reg .u64 t; cvta.to.shared.u64 t, %1; cvt.u32.u64 %0, t;}" : "=r"(r) : "l"(p));
    return r;
}
__device__ __forceinline__ void cpa4(u32 dst, const float* src) {
    asm volatile("cp.async.ca.shared.global [%0], [%1], 4;" :: "r"(dst), "l"(src));
}
#define CP_COMMIT() asm volatile("cp.async.commit_group;" ::: "memory")
#define CP_WAIT(n)  asm volatile("cp.async.wait_group %0;" :: "n"(n) : "memory")

// async-stage one chunk's x window (32-halo included) for both rows; 4B LDGSTS, no reg stall
__device__ __forceinline__ void stage(float* r0, float* r1, int c0, int tid,
                                      const float* __restrict__ x0,
                                      const float* __restrict__ x1) {
    u32 d0 = sptr(r0), d1 = sptr(r1);
    const bool skip0 = (c0 == 0);   // halo floats 0..31 have no source; zero-fixed later
    // floats fi = tid + 128*it ; sw(fi+128) = sw(fi) + 136  (128 = 8*16)
    {
        int fi = tid; u32 a = d0 + 4u * (u32)sw(tid);
#pragma unroll
        for (int it = 0; it < 17; it++) {
            if (fi < IN_F && !(skip0 && fi < 32)) cpa4(a, x0 + (c0 - 32) + fi);
            fi += TPB; a += 136u * 4u;
        }
    }
    {
        int fi = tid; u32 a = d1 + 4u * (u32)sw(tid);
#pragma unroll
        for (int it = 0; it < 17; it++) {
            if (fi < IN_F && !(skip0 && fi < 32)) cpa4(a, x1 + (c0 - 32) + fi);
            fi += TPB; a += 136u * 4u;
        }
    }
}

__global__ void __launch_bounds__(TPB, 4) fir2(const float* __restrict__ x,
                                               const float* __restrict__ h,
                                               float* __restrict__ y) {
    __shared__ __align__(16) float sX[2][2][ROW_F];  // [buf][row][padded floats]
    __shared__ u64 sB[4][16];     // warp-boundary v (lane31 -> next warp's lane0)
    __shared__ u64 sHv[16];       // chunk-boundary v halo (recomputed from x)

    const int tid  = threadIdx.x;
    const int lane = tid & 31;
    const int wid  = tid >> 5;
    const int pair = blockIdx.y;
    const int cb0  = blockIdx.x * (NCHUNK * CHUNK);
    const float* __restrict__ x0 = x + (size_t)(2 * pair) * N_LEN;
    const float* __restrict__ x1 = x0 + N_LEN;
    float* __restrict__ y0 = y + (size_t)(2 * pair) * N_LEN;
    float* __restrict__ y1 = y0 + N_LEN;

    // 16 packed coefficients (h[j],h[j]); pass 2 indexes reversed as h[15-j]
    u64 gph[16];
#pragma unroll
    for (int j = 0; j < 16; j++) { float hv = __ldg(h + j); gph[j] = pack2(hv, hv); }

    // prologue: stage chunk 0
    stage(sX[0][0], sX[0][1], cb0, tid, x0, x1); CP_COMMIT();

    float* curR0 = sX[0][0]; float* curR1 = sX[0][1];
    float* nxtR0 = sX[1][0]; float* nxtR1 = sX[1][1];

#pragma unroll 1
    for (int cc = 0; cc < NCHUNK; cc++) {
        const int c0 = cb0 + cc * CHUNK;
        const bool kill = (c0 == 0) && (tid == 0);

        if (cc + 1 < NCHUNK) {            // prefetch next chunk, fully async
            stage(nxtR0, nxtR1, c0 + CHUNK, tid, x0, x1); CP_COMMIT();
            CP_WAIT(1);                   // current chunk's group complete
        } else {
            CP_WAIT(0);
        }
        if (c0 == 0 && tid < 32) {        // zero-fix missing halo (block 0, chunk 0)
            curR0[sw(tid)] = 0.f; curR1[sw(tid)] = 0.f;
        }
        __syncthreads();                  // cur fully staged & visible

        // ---- pass 1: v[p] = x[p] + sum_{j=0..15} h[j]*x[p-1-j]; kept in regs ----
        u64 vbuf[16];
        {
            u64 r[16];
            const int wA = 17 * (tid + 1);            // sw(lo+16+s) = 17(tid+1)+s
#pragma unroll
            for (int s = 0; s < 16; s++) r[s] = pack2(curR0[wA + s], curR1[wA + s]);

            const int xA = 17 * (tid + 2);            // sw(lo+32+t) = 17(tid+2)+t
#pragma unroll
            for (int t = 0; t < EPT; t++) {
                u64 xi = pack2(curR0[xA + t], curR1[xA + t]);
                u64 acc0 = xi;
#pragma unroll
                for (int j = 0; j < 8; j++)
                    acc0 = fma2(gph[j], r[(t + 15 - j) & 15], acc0);
                u64 acc1 = mul2(gph[8], r[(t + 7) & 15]);
#pragma unroll
                for (int j = 9; j < 16; j++)
                    acc1 = fma2(gph[j], r[(t + 15 - j) & 15], acc1);
                vbuf[t] = add2(acc0, acc1);
                r[t & 15] = xi;
            }
        }
        if (kill) {
#pragma unroll
            for (int t = 0; t < EPT; t++) vbuf[t] = 0ULL;
        }

        // publish warp-boundary v (lane31 -> sB) for next warp's lane0
        if (lane == 31) {
#pragma unroll
            for (int s = 0; s < 16; s++) sB[wid][s] = vbuf[s];
        }
        // chunk-boundary v halo: v[c0-16+tid] recomputed from x (tid<16)
        if (tid < 16) {
            u64 v = 0ULL;
            if (c0 - 16 + tid >= 16) {                // pos >= 16 -> unmasked
                u64 xi = pack2(curR0[sw(16 + tid)], curR1[sw(16 + tid)]);
                u64 a0 = xi;
#pragma unroll
                for (int j = 0; j < 8; j++) {
                    int ix = sw(15 + tid - j);
                    a0 = fma2(gph[j], pack2(curR0[ix], curR1[ix]), a0);
                }
                u64 a1;
                { int ix = sw(7 + tid); a1 = mul2(gph[8], pack2(curR0[ix], curR1[ix])); }
#pragma unroll
                for (int j = 9; j < 16; j++) {
                    int ix = sw(15 + tid - j);
                    a1 = fma2(gph[j], pack2(curR0[ix], curR1[ix]), a1);
                }
                v = add2(a0, a1);
            }
            sHv[tid] = v;
        }
        __syncthreads();                  // sB/sHv visible; all x reads of cur done

        // ---- pass 2: y[p] = v[p] + sum_j h[15-j]*v[p-1-j]; halo via shfl ----
        {
            u64 hv[16];
#pragma unroll
            for (int s = 0; s < 16; s++)
                hv[s] = __shfl_up_sync(0xffffffffu, vbuf[s], 1);
            if (lane == 0) {
                if (wid > 0) {
#pragma unroll
                    for (int s = 0; s < 16; s++) hv[s] = sB[wid - 1][s];
                } else {
#pragma unroll
                    for (int s = 0; s < 16; s++) hv[s] = sHv[s];
                }
            }

            const int yA = 17 * tid;                  // sw(lo+t) = 17*tid + t
#pragma unroll
            for (int t = 0; t < EPT; t++) {
                u64 acc0 = vbuf[t];
#pragma unroll
                for (int j = 0; j < 8; j++) {
                    int k = t - 1 - j;
                    u64 tap = (k >= 0) ? vbuf[k] : hv[16 + k];
                    acc0 = fma2(gph[15 - j], tap, acc0);
                }
                u64 tap8;
                { int k = t - 9; tap8 = (k >= 0) ? vbuf[k] : hv[16 + k]; }
                u64 acc1 = mul2(gph[7], tap8);
#pragma unroll
                for (int j = 9; j < 16; j++) {
                    int k = t - 1 - j;
                    u64 tap = (k >= 0) ? vbuf[k] : hv[16 + k];
                    acc1 = fma2(gph[15 - j], tap, acc1);
                }
                u64 yv = add2(acc0, acc1);
                if (kill) yv = 0ULL;                  // positions 0..15 masked
                float ya, yb; unpack2(yv, ya, yb);
                curR0[yA + t] = ya;                   // stage y over dead x region
                curR1[yA + t] = yb;
            }
        }
        __syncthreads();                  // y staged

        // ---- writeout: scalar LDS gathers (odd-pad layout), coalesced STG.128 ----
#pragma unroll
        for (int it = 0; it < 4; it++) {
            int fi = 4 * (tid + it * TPB);            // 4-float group base, 16B-aligned in gmem
            int ix = 17 * (fi >> 4) + (fi & 15);      // (fi&15) in {0,4,8,12}: stays in group
            float4 a = make_float4(curR0[ix], curR0[ix + 1], curR0[ix + 2], curR0[ix + 3]);
            float4 b = make_float4(curR1[ix], curR1[ix + 1], curR1[ix + 2], curR1[ix + 3]);
            *reinterpret_cast<float4*>(y0 + c0 + fi) = a;
            *reinterpret_cast<float4*>(y1 + c0 + fi) = b;
        }
        __syncthreads();                  // cur free before it becomes a staging target

        // swap buffers
        float* t0 = curR0; float* t1 = curR1;
        curR0 = nxtR0; curR1 = nxtR1;
        nxtR0 = t0;    nxtR1 = t1;
    }
}

extern "C" void kernel_launch(void* const* d_in, const int* in_sizes, int n_in,
                              void* d_out, int out_size) {
    (void)in_sizes; (void)n_in; (void)out_size;
    const float* x = (const float*)d_in[0];
    const float* h = (const float*)d_in[1];
    float* y = (float*)d_out;

    dim3 grid(N_LEN / (CHUNK * NCHUNK), B_ROWS / 2, 1);
    fir2<<<grid, TPB>>>(x, h, y);
}

// round 10
// speedup vs baseline: 1.2971x; 1.1834x over previous
#include <cuda_runtime.h>

// Problem constants
#define N_LEN   131072
#define B_ROWS  256

// Tiling: each WARP owns one 512-position tile of a row-pair, fully autonomously.
#define TPB     128
#define NWARP   4
#define WTILE   512                    // positions per warp tile
#define EPT     16                     // positions per lane
#define W_IN    (WTILE + 32)           // 544 x-pairs incl 32-halo
#define PAD16(n) ((((n) + 15) / 16) * 17)
#define W_PAD   PAD16(W_IN)            // 578 u64 slots per warp

typedef unsigned long long u64;

__device__ __forceinline__ u64 pack2(float a, float b) {
    u64 r; asm("mov.b64 %0,{%1,%2};" : "=l"(r) : "f"(a), "f"(b)); return r;
}
__device__ __forceinline__ void unpack2(u64 v, float& a, float& b) {
    asm("mov.b64 {%0,%1},%2;" : "=f"(a), "=f"(b) : "l"(v));
}
__device__ __forceinline__ u64 fma2(u64 a, u64 b, u64 c) {
    u64 d; asm("fma.rn.f32x2 %0,%1,%2,%3;" : "=l"(d) : "l"(a), "l"(b), "l"(c)); return d;
}
__device__ __forceinline__ u64 mul2(u64 a, u64 b) {
    u64 d; asm("mul.rn.f32x2 %0,%1,%2;" : "=l"(d) : "l"(a), "l"(b)); return d;
}
__device__ __forceinline__ u64 add2(u64 a, u64 b) {
    u64 d; asm("add.rn.f32x2 %0,%1,%2;" : "=l"(d) : "l"(a), "l"(b)); return d;
}

// pad-17-per-16 swizzle on u64 slots (2-way worst case for stride-16 patterns)
__device__ __forceinline__ int sw(int k) { return (k >> 4) * 17 + (k & 15); }

__global__ void __launch_bounds__(TPB, 4) fir2(const float* __restrict__ x,
                                               const float* __restrict__ h,
                                               float* __restrict__ y) {
    __shared__ u64 sX[NWARP][W_PAD];   // per-warp x window; reused for y staging
    __shared__ u64 sHv[NWARP][16];     // per-warp tile-boundary v halo

    const int tid  = threadIdx.x;
    const int lane = tid & 31;
    const int wid  = tid >> 5;
    const int pair = blockIdx.y;
    const int c0   = blockIdx.x * (NWARP * WTILE) + wid * WTILE;  // warp tile base
    const float* __restrict__ x0 = x + (size_t)(2 * pair) * N_LEN;
    const float* __restrict__ x1 = x0 + N_LEN;
    float* __restrict__ y0 = y + (size_t)(2 * pair) * N_LEN;
    float* __restrict__ y1 = y0 + N_LEN;

    u64* sIn = sX[wid];                // slot k <-> x[c0 - 32 + k]

    // 16 packed coefficients (h[j],h[j]); pass 2 indexes reversed as h[15-j]
    u64 gph[16];
#pragma unroll
    for (int j = 0; j < 16; j++) { float hv = __ldg(h + j); gph[j] = pack2(hv, hv); }

    // ---- stage x: LDG.128 both rows, pack to u64 pairs, STS.64 (warp-private) ----
#pragma unroll
    for (int it = 0; it < 5; it++) {
        int g = lane + it * 32;        // float4 group, 136 groups of 4 pairs
        if (g < W_IN / 4) {
            int p = c0 - 32 + 4 * g;   // 16B-aligned; <0 only for the first tile
            float4 a0, a1;
            if (p >= 0) {
                a0 = *reinterpret_cast<const float4*>(x0 + p);
                a1 = *reinterpret_cast<const float4*>(x1 + p);
            } else {
                a0 = make_float4(0.f, 0.f, 0.f, 0.f);
                a1 = make_float4(0.f, 0.f, 0.f, 0.f);
            }
            int ph = sw(4 * g);        // (4g&15)<=12 -> 4 contiguous slots
            sIn[ph + 0] = pack2(a0.x, a1.x);
            sIn[ph + 1] = pack2(a0.y, a1.y);
            sIn[ph + 2] = pack2(a0.z, a1.z);
            sIn[ph + 3] = pack2(a0.w, a1.w);
        }
    }
    __syncwarp(0xffffffffu);

    const int lo = lane * EPT;
    const bool kill = (c0 == 0) && (lane == 0);     // positions 0..15 masked to 0

    // ---- pass 1: v[p] = x[p] + sum_{j=0..15} h[j]*x[p-1-j]; kept in regs ----
    u64 vbuf[16];
    {
        u64 r[16];                     // x ring: local pos q at slot q&15
#pragma unroll
        for (int s = 0; s < 16; s++) r[s] = sIn[sw(lo + 16 + s)];   // x[c0+lo-16+s]

#pragma unroll
        for (int t = 0; t < EPT; t++) {
            u64 xi = sIn[sw(lo + 32 + t)];          // x[c0+lo+t]
            u64 acc0 = xi;
#pragma unroll
            for (int j = 0; j < 8; j++)
                acc0 = fma2(gph[j], r[(t + 15 - j) & 15], acc0);
            u64 acc1 = mul2(gph[8], r[(t + 7) & 15]);
#pragma unroll
            for (int j = 9; j < 16; j++)
                acc1 = fma2(gph[j], r[(t + 15 - j) & 15], acc1);
            vbuf[t] = add2(acc0, acc1);
            r[t & 15] = xi;
        }
    }
    if (kill) {
#pragma unroll
        for (int t = 0; t < EPT; t++) vbuf[t] = 0ULL;
    }

    // ---- tile-boundary v halo: v[c0-16+s] recomputed from x (lanes 0..15) ----
    if (lane < 16) {
        u64 v = 0ULL;
        if (c0 - 16 + lane >= 16) {                 // pos>=16 -> unmasked
            u64 xi = sIn[sw(16 + lane)];            // x[c0-16+lane]
            u64 a0 = xi;
#pragma unroll
            for (int j = 0; j < 8; j++)  a0 = fma2(gph[j], sIn[sw(15 + lane - j)], a0);
            u64 a1 = mul2(gph[8], sIn[sw(7 + lane)]);
#pragma unroll
            for (int j = 9; j < 16; j++) a1 = fma2(gph[j], sIn[sw(15 + lane - j)], a1);
            v = add2(a0, a1);
        }
        sHv[wid][lane] = v;
    }
    __syncwarp(0xffffffffu);           // sHv visible; all x reads done before y overwrites

    // ---- pass 2: y[p] = v[p] + sum_j h[15-j]*v[p-1-j]; halo via shfl ----
    {
        u64 hv[16];                    // v[lo-16+s]: previous lane's vbuf
#pragma unroll
        for (int s = 0; s < 16; s++)
            hv[s] = __shfl_up_sync(0xffffffffu, vbuf[s], 1);
        if (lane == 0) {
#pragma unroll
            for (int s = 0; s < 16; s++) hv[s] = sHv[wid][s];
        }

        const int yA = 17 * lane;      // y local pos lo+t -> slot sw(lo+t) = 17*lane + t
#pragma unroll
        for (int t = 0; t < EPT; t++) {
            u64 acc0 = vbuf[t];
#pragma unroll
            for (int j = 0; j < 8; j++) {
                int k = t - 1 - j;
                u64 tap = (k >= 0) ? vbuf[k] : hv[16 + k];
                acc0 = fma2(gph[15 - j], tap, acc0);
            }
            u64 tap8;
            { int k = t - 9; tap8 = (k >= 0) ? vbuf[k] : hv[16 + k]; }
            u64 acc1 = mul2(gph[7], tap8);
#pragma unroll
            for (int j = 9; j < 16; j++) {
                int k = t - 1 - j;
                u64 tap = (k >= 0) ? vbuf[k] : hv[16 + k];
                acc1 = fma2(gph[15 - j], tap, acc1);
            }
            u64 yv = add2(acc0, acc1);
            if (kill) yv = 0ULL;       // positions 0..15 masked
            sIn[yA + t] = yv;          // stage y over dead x region
        }
    }
    __syncwarp(0xffffffffu);           // y staged

    // ---- writeout: gather u64 slots, coalesced STG.128 per row ----
#pragma unroll
    for (int it = 0; it < 4; it++) {
        int g  = lane + it * 32;       // 4-pair group, 128 groups
        int fi = 4 * g;
        int ix = 17 * (fi >> 4) + (fi & 15);        // contiguous 4 slots
        float a[4], b[4];
#pragma unroll
        for (int k = 0; k < 4; k++) unpack2(sIn[ix + k], a[k], b[k]);
        *reinterpret_cast<float4*>(y0 + c0 + fi) = make_float4(a[0], a[1], a[2], a[3]);
        *reinterpret_cast<float4*>(y1 + c0 + fi) = make_float4(b[0], b[1], b[2], b[3]);
    }
}

extern "C" void kernel_launch(void* const* d_in, const int* in_sizes, int n_in,
                              void* d_out, int out_size) {
    (void)in_sizes; (void)n_in; (void)out_size;
    const float* x = (const float*)d_in[0];
    const float* h = (const float*)d_in[1];
    float* y = (float*)d_out;

    dim3 grid(N_LEN / (NWARP * WTILE), B_ROWS / 2, 1);
    fir2<<<grid, TPB>>>(x, h, y);
}